// round 17
// baseline (speedup 1.0000x reference)
#include <cuda_runtime.h>
#include <cstdint>

// Problem constants
constexpr int B = 2, S = 2048, HID = 2048, NH = 16, NKV = 4, HD = 128;
constexpr int M = B * S;
constexpr int KW = HID / 2;  // 1024 fp16-pair words per GEMM row (K=2048)

// fp32 scratch (rope/vconv inputs)
__device__ float g_q[(size_t)B * S * NH * HD];
__device__ float g_k[(size_t)B * S * NKV * HD];
__device__ float g_v[(size_t)B * S * NKV * HD];
// RoPE tables (fp32, computed once in double)
__device__ float g_cos[(size_t)S * 64];
__device__ float g_sin[(size_t)S * 64];
// fp16 packed (1 word = 2 fp16) GEMM operands
__device__ uint32_t g_hsh[(size_t)M * KW];
__device__ uint32_t g_wqh[(size_t)(NH * HD) * KW];
__device__ uint32_t g_wkh[(size_t)(NKV * HD) * KW];
__device__ uint32_t g_wvh[(size_t)(NKV * HD) * KW];
__device__ uint32_t g_woh[(size_t)HID * KW];
__device__ uint32_t g_ah[(size_t)M * KW];
// fp16 packed attention-ready buffers
__device__ uint32_t g_qh[(size_t)B * S * NH * 64];
__device__ uint32_t g_kh[(size_t)B * NKV * S * 64];
__device__ uint32_t g_vh[(size_t)B * NKV * (S / 2) * 128];

// ---------------- helpers ----------------
__device__ __forceinline__ uint32_t cvt2h(float lo_e, float hi_e) {
    uint32_t r;
    asm("cvt.rn.f16x2.f32 %0, %1, %2;" : "=r"(r) : "f"(hi_e), "f"(lo_e));
    return r;
}
__device__ __forceinline__ void mmah(float* c, const uint32_t* a, const uint32_t* b) {
    asm volatile(
        "mma.sync.aligned.m16n8k16.row.col.f32.f16.f16.f32 "
        "{%0,%1,%2,%3}, {%4,%5,%6,%7}, {%8,%9}, {%0,%1,%2,%3};"
        : "+f"(c[0]), "+f"(c[1]), "+f"(c[2]), "+f"(c[3])
        : "r"(a[0]), "r"(a[1]), "r"(a[2]), "r"(a[3]), "r"(b[0]), "r"(b[1]));
}
__device__ __forceinline__ uint32_t smem_u32(const void* p) {
    uint32_t a;
    asm("{ .reg .u64 t; cvta.to.shared.u64 t, %1; cvt.u32.u64 %0, t; }" : "=r"(a) : "l"(p));
    return a;
}
#define CP16(dst, src) \
    asm volatile("cp.async.cg.shared.global [%0], [%1], 16;" :: "r"(dst), "l"(src) : "memory")
#define CP_COMMIT() asm volatile("cp.async.commit_group;" ::: "memory")
#define CP_WAIT0() asm volatile("cp.async.wait_group 0;" ::: "memory")
#define CP_WAIT2() asm volatile("cp.async.wait_group 2;" ::: "memory")

// ---------------- fused prep: weight pack + hs pack + rope table ----------------
constexpr int NW_WQ = NH * HD * KW;
constexpr int NW_WK = NKV * HD * KW;
constexpr int NW_WV = NW_WK;
constexpr int NW_WO = HID * KW;
constexpr int NW_W = NW_WQ + NW_WK + NW_WV + NW_WO;
constexpr int NW_HS = M * KW;
constexpr int N_TBL = S * 64;
constexpr int N_PREP = NW_W + NW_HS + N_TBL;

__global__ void prep_kernel(const float* __restrict__ hs,
                            const float* __restrict__ Wq, const float* __restrict__ Wk,
                            const float* __restrict__ Wv, const float* __restrict__ Wo) {
    int i = blockIdx.x * blockDim.x + threadIdx.x;
    if (i >= N_PREP) return;
    if (i < NW_W) {
        const float* src;
        uint32_t* dst;
        int j = i;
        if (j < NW_WQ) { src = Wq; dst = g_wqh; }
        else if ((j -= NW_WQ) < NW_WK) { src = Wk; dst = g_wkh; }
        else if ((j -= NW_WK) < NW_WV) { src = Wv; dst = g_wvh; }
        else { j -= NW_WV; src = Wo; dst = g_woh; }
        const float2 v = *(const float2*)(src + 2 * (size_t)j);
        dst[j] = cvt2h(v.x, v.y);
    } else if (i < NW_W + NW_HS) {
        const int j = i - NW_W;
        const float2 v = *(const float2*)(hs + 2 * (size_t)j);
        g_hsh[j] = cvt2h(v.x, v.y);
    } else {
        const int idx = i - NW_W - NW_HS;
        const int p = idx & 63, s = idx >> 6;
        const double ang = (double)s * pow(10000.0, -(double)p / 64.0);
        double sd, cd;
        sincos(ang, &sd, &cd);
        g_cos[idx] = (float)cd;
        g_sin[idx] = (float)sd;
    }
}

// ================= fp16 GEMM, 4-stage cp.async, single barrier/iter (R16) =================
constexpr int ROW_W = 20;
constexpr int TILE_W = 128 * ROW_W;
constexpr int STAGE_W = 2 * TILE_W;
constexpr int NSTAGE = 4;
constexpr int GEMM_SMEM = NSTAGE * STAGE_W * 4;  // 81920 B (2 CTAs: 160K < 228K)
constexpr int T_A = 0, T_B = TILE_W;

__device__ __forceinline__ void gemm_body(
    const uint32_t* __restrict__ A, const uint32_t* __restrict__ Bw,
    const float* __restrict__ bias, float* __restrict__ C,
    int N, int m0, int n0, uint32_t* smw, uint32_t swb)
{
    const int tid = threadIdx.x;
    const int lane = tid & 31;
    const int w = tid >> 5;
    const int wm = w & 1, wn = w >> 1;
    const int NIT = KW / 16;

    float acc[4][4][4];
#pragma unroll
    for (int mt = 0; mt < 4; mt++)
#pragma unroll
        for (int nt = 0; nt < 4; nt++)
#pragma unroll
            for (int r = 0; r < 4; r++) acc[mt][nt][r] = 0.f;

    auto cpstage = [&](int it, int st) {
        const uint32_t ad = swb + (st * STAGE_W + T_A) * 4;
        const uint32_t bd = swb + (st * STAGE_W + T_B) * 4;
        const int k0 = it * 16;
#pragma unroll
        for (int i = 0; i < 2; i++) {
            const int idx = tid + i * 256;
            const int r = idx >> 2, c = idx & 3;
            CP16(ad + (r * ROW_W + c * 4) * 4, A + (size_t)(m0 + r) * KW + k0 + c * 4);
            CP16(bd + (r * ROW_W + c * 4) * 4, Bw + (size_t)(n0 + r) * KW + k0 + c * 4);
        }
    };

#pragma unroll
    for (int s = 0; s < NSTAGE - 1; s++) {
        cpstage(s, s);
        CP_COMMIT();
    }

    const int arow = wm * 64 + (lane >> 2);
    const int brow = wn * 32 + (lane >> 2);
    const int kq = lane & 3;

    for (int it = 0; it < NIT; it++) {
        CP_WAIT2();
        __syncthreads();
        if (it + NSTAGE - 1 < NIT) cpstage(it + NSTAGE - 1, (it + NSTAGE - 1) & 3);
        CP_COMMIT();
        uint32_t* buf = smw + (it & 3) * STAGE_W;

#pragma unroll
        for (int ks = 0; ks < 2; ks++) {
            const int kw = ks * 8 + kq;
            uint32_t ah[4][4], bh[4][2];
#pragma unroll
            for (int mt = 0; mt < 4; mt++) {
                const int base = T_A + (arow + mt * 16) * ROW_W + kw;
                ah[mt][0] = buf[base];
                ah[mt][1] = buf[base + 8 * ROW_W];
                ah[mt][2] = buf[base + 4];
                ah[mt][3] = buf[base + 8 * ROW_W + 4];
            }
#pragma unroll
            for (int nt = 0; nt < 4; nt++) {
                const int base = T_B + (brow + nt * 8) * ROW_W + kw;
                bh[nt][0] = buf[base];
                bh[nt][1] = buf[base + 4];
            }
#pragma unroll
            for (int mt = 0; mt < 4; mt++)
#pragma unroll
                for (int nt = 0; nt < 4; nt++)
                    mmah(acc[mt][nt], ah[mt], bh[nt]);
        }
    }

#pragma unroll
    for (int mt = 0; mt < 4; mt++) {
        const int r0 = m0 + wm * 64 + mt * 16 + (lane >> 2);
#pragma unroll
        for (int nt = 0; nt < 4; nt++) {
            const int cc = n0 + wn * 32 + nt * 8 + (lane & 3) * 2;
            float b0 = 0.f, b1 = 0.f;
            if (bias) { b0 = bias[cc]; b1 = bias[cc + 1]; }
            *(float2*)(C + (size_t)r0 * N + cc) =
                make_float2(acc[mt][nt][0] + b0, acc[mt][nt][1] + b1);
            *(float2*)(C + (size_t)(r0 + 8) * N + cc) =
                make_float2(acc[mt][nt][2] + b0, acc[mt][nt][3] + b1);
        }
    }
}

__global__ __launch_bounds__(256, 2) void gemm_qkv(
    const float* __restrict__ bq, const float* __restrict__ bk,
    const float* __restrict__ bv,
    float* __restrict__ qp, float* __restrict__ kp, float* __restrict__ vp)
{
    extern __shared__ uint32_t smw[];
    const uint32_t swb = smem_u32(smw);
    const int bx = blockIdx.x;
    const int m0 = blockIdx.y * 128;
    if (bx < 16) {
        gemm_body(g_hsh, g_wqh, bq, qp, NH * HD, m0, bx * 128, smw, swb);
    } else if (bx < 20) {
        gemm_body(g_hsh, g_wkh, bk, kp, NKV * HD, m0, (bx - 16) * 128, smw, swb);
    } else {
        gemm_body(g_hsh, g_wvh, bv, vp, NKV * HD, m0, (bx - 20) * 128, smw, swb);
    }
}

__global__ __launch_bounds__(256, 2) void gemm_o(float* __restrict__ C) {
    extern __shared__ uint32_t smw[];
    const uint32_t swb = smem_u32(smw);
    gemm_body(g_ah, g_woh, nullptr, C, HID, blockIdx.y * 128, blockIdx.x * 128, smw, swb);
}

// ---------------- fused RoPE apply + V pack ----------------
constexpr int N_ROPE = B * S * (NH + NKV) * 32;
constexpr int N_VC = B * NKV * (S / 2) * 32;

__global__ void rope_vconv_kernel() {
    int gi = blockIdx.x * blockDim.x + threadIdx.x;
    if (gi < N_ROPE) {
        const int idx = gi;
        const int p2 = idx & 31;
        const int p = p2 * 2;
        const int h = (idx >> 5) % (NH + NKV);
        const int rem = (idx >> 5) / (NH + NKV);
        const int s = rem % S;
        const int b = rem / S;
        const float c0 = g_cos[s * 64 + p], sn0 = g_sin[s * 64 + p];
        const float c1 = g_cos[s * 64 + p + 1], sn1 = g_sin[s * 64 + p + 1];
        if (h < NH) {
            const float* base = g_q + ((size_t)((b * S + s) * NH + h)) * HD;
            const float x0 = base[p], x1 = base[p + 1];
            const float y0 = base[p + 64], y1 = base[p + 65];
            const float scale = 0.08838834764831845f;
            uint32_t* qo = g_qh + ((size_t)((b * S + s) * NH + h)) * 64;
            qo[p2] = cvt2h((x0 * c0 - y0 * sn0) * scale, (x1 * c1 - y1 * sn1) * scale);
            qo[32 + p2] = cvt2h((y0 * c0 + x0 * sn0) * scale, (y1 * c1 + x1 * sn1) * scale);
        } else {
            const int kh = h - NH;
            const float* base = g_k + ((size_t)((b * S + s) * NKV + kh)) * HD;
            const float x0 = base[p], x1 = base[p + 1];
            const float y0 = base[p + 64], y1 = base[p + 65];
            uint32_t* ko = g_kh + ((size_t)((b * NKV + kh) * S + s)) * 64;
            ko[p2] = cvt2h(x0 * c0 - y0 * sn0, x1 * c1 - y1 * sn1);
            ko[32 + p2] = cvt2h(y0 * c0 + x0 * sn0, y1 * c1 + x1 * sn1);
        }
    } else if (gi < N_ROPE + N_VC) {
        const int idx = gi - N_ROPE;
        const int c = idx & 31, d0 = c * 4;
        const int kwp = (idx >> 5) % (S / 2);
        const int t2 = (idx >> 5) / (S / 2);
        const int kh = t2 % NKV, b = t2 / NKV;
        const float* base = g_v + ((size_t)((b * S + 2 * kwp) * NKV + kh)) * HD + d0;
        const float4 va = *(const float4*)base;
        const float4 vb = *(const float4*)(base + (size_t)NKV * HD);
        uint32_t* vo = g_vh + ((size_t)((b * NKV + kh) * (S / 2) + kwp)) * 128 + d0;
        *(uint4*)vo = make_uint4(cvt2h(va.x, vb.x), cvt2h(va.y, vb.y),
                                 cvt2h(va.z, vb.z), cvt2h(va.w, vb.w));
    }
}

// ================= Flash attention: single-barrier pipeline, register-P =================
constexpr int QT = 64, KT = 64;
constexpr int QROW = 68, KROW = 68, VROW = 136;
constexpr int A_Q = 0;
constexpr int A_K0 = A_Q + QT * QROW;
constexpr int A_V0 = A_K0 + 2 * KT * KROW;
constexpr int ATTN_SMEM = (A_V0 + 2 * 32 * VROW) * 4;  // 87040 B

__global__ __launch_bounds__(128, 2) void attn_mma() {
    extern __shared__ uint32_t sw[];
    const uint32_t swb = smem_u32(sw);
    const int q0 = (gridDim.x - 1 - blockIdx.x) * QT;
    const int h = blockIdx.y, b = blockIdx.z;
    const int kh = h >> 2;
    const int tid = threadIdx.x;
    const int lane = tid & 31, w = tid >> 5;
    const int r4 = lane >> 2, cq = lane & 3;

    const uint32_t* kbase = g_kh + ((size_t)(b * NKV + kh)) * S * 64;
    const uint32_t* vbase = g_vh + ((size_t)(b * NKV + kh)) * (S / 2) * 128;

    auto copyKV = [&](int t, int st) {
        const uint32_t kdst0 = swb + (A_K0 + st * KT * KROW) * 4;
        const uint32_t vdst0 = swb + (A_V0 + st * 32 * VROW) * 4;
        const uint32_t* kg = kbase + (size_t)t * KT * 64;
        const uint32_t* vg = vbase + (size_t)t * 32 * 128;
#pragma unroll
        for (int i = 0; i < 8; i++) {
            const int c = tid + i * 128;
            const int kr = c >> 4, kc = c & 15;
            CP16(kdst0 + (kr * KROW + kc * 4) * 4, kg + kr * 64 + kc * 4);
            const int vr = c >> 5, vc = c & 31;
            CP16(vdst0 + (vr * VROW + vc * 4) * 4, vg + vr * 128 + vc * 4);
        }
    };

    {
#pragma unroll
        for (int i = 0; i < 8; i++) {
            const int c = tid + i * 128;
            const int r = c >> 4, cc = c & 15;
            CP16(swb + (A_Q + r * QROW + cc * 4) * 4,
                 g_qh + ((size_t)((b * S + q0 + r) * NH + h)) * 64 + cc * 4);
        }
        copyKV(0, 0);
        CP_COMMIT();
    }

    float o[16][4];
#pragma unroll
    for (int nt = 0; nt < 16; nt++)
#pragma unroll
        for (int r = 0; r < 4; r++) o[nt][r] = 0.f;
    float m0 = -1e30f, m1 = -1e30f, l0 = 0.f, l1 = 0.f;

    const int ntiles = (q0 >> 6) + 1;

    for (int t = 0; t < ntiles; t++) {
        // Single barrier per tile: stage t complete -> sync -> prefetch t+1.
        // Copy for t+1 targets stage (t+1)&1, last read at tile t-1; the
        // barrier at t guarantees those reads are done (warps only arrive
        // after finishing tile t-1's compute).
        CP_WAIT0();
        __syncthreads();
        if (t + 1 < ntiles) {
            copyKV(t + 1, (t + 1) & 1);
            CP_COMMIT();
        }
        const int kb = A_K0 + (t & 1) * KT * KROW;
        const int vb = A_V0 + (t & 1) * 32 * VROW;

        float sc[8][4];
#pragma unroll
        for (int nt = 0; nt < 8; nt++)
#pragma unroll
            for (int r = 0; r < 4; r++) sc[nt][r] = 0.f;
#pragma unroll
        for (int ks = 0; ks < 8; ks++) {
            uint32_t ah[4];
            const int base = A_Q + (w * 16 + r4) * QROW + ks * 8 + cq;
            ah[0] = sw[base];
            ah[1] = sw[base + 8 * QROW];
            ah[2] = sw[base + 4];
            ah[3] = sw[base + 8 * QROW + 4];
#pragma unroll
            for (int nt = 0; nt < 8; nt++) {
                const int nb = kb + (nt * 8 + r4) * KROW + ks * 8 + cq;
                uint32_t bh[2] = {sw[nb], sw[nb + 4]};
                mmah(sc[nt], ah, bh);
            }
        }
        if (t == ntiles - 1) {
            const int n0 = t * KT;
            const int row0 = q0 + w * 16 + r4, row1 = row0 + 8;
#pragma unroll
            for (int nt = 0; nt < 8; nt++) {
                const int col0 = n0 + nt * 8 + 2 * cq;
                if (col0 > row0) sc[nt][0] = -1e30f;
                if (col0 + 1 > row0) sc[nt][1] = -1e30f;
                if (col0 > row1) sc[nt][2] = -1e30f;
                if (col0 + 1 > row1) sc[nt][3] = -1e30f;
            }
        }
        float rx0 = -1e30f, rx1 = -1e30f;
#pragma unroll
        for (int nt = 0; nt < 8; nt++) {
            rx0 = fmaxf(rx0, fmaxf(sc[nt][0], sc[nt][1]));
            rx1 = fmaxf(rx1, fmaxf(sc[nt][2], sc[nt][3]));
        }
        rx0 = fmaxf(rx0, __shfl_xor_sync(0xffffffffu, rx0, 1));
        rx0 = fmaxf(rx0, __shfl_xor_sync(0xffffffffu, rx0, 2));
        rx1 = fmaxf(rx1, __shfl_xor_sync(0xffffffffu, rx1, 1));
        rx1 = fmaxf(rx1, __shfl_xor_sync(0xffffffffu, rx1, 2));
        const float mn0 = fmaxf(m0, rx0), mn1 = fmaxf(m1, rx1);
        const float f0 = __expf(m0 - mn0), f1 = __expf(m1 - mn1);
        float rs0 = 0.f, rs1 = 0.f;
#pragma unroll
        for (int nt = 0; nt < 8; nt++) {
            sc[nt][0] = __expf(sc[nt][0] - mn0);
            sc[nt][1] = __expf(sc[nt][1] - mn0);
            sc[nt][2] = __expf(sc[nt][2] - mn1);
            sc[nt][3] = __expf(sc[nt][3] - mn1);
            rs0 += sc[nt][0] + sc[nt][1];
            rs1 += sc[nt][2] + sc[nt][3];
        }
        rs0 += __shfl_xor_sync(0xffffffffu, rs0, 1);
        rs0 += __shfl_xor_sync(0xffffffffu, rs0, 2);
        rs1 += __shfl_xor_sync(0xffffffffu, rs1, 1);
        rs1 += __shfl_xor_sync(0xffffffffu, rs1, 2);
        l0 = l0 * f0 + rs0;
        l1 = l1 * f1 + rs1;
        m0 = mn0; m1 = mn1;
#pragma unroll
        for (int nt = 0; nt < 16; nt++) {
            o[nt][0] *= f0; o[nt][1] *= f0;
            o[nt][2] *= f1; o[nt][3] *= f1;
        }
#pragma unroll
        for (int ks = 0; ks < 4; ks++) {
            uint32_t ah[4];
            ah[0] = cvt2h(sc[2 * ks][0], sc[2 * ks][1]);
            ah[1] = cvt2h(sc[2 * ks][2], sc[2 * ks][3]);
            ah[2] = cvt2h(sc[2 * ks + 1][0], sc[2 * ks + 1][1]);
            ah[3] = cvt2h(sc[2 * ks + 1][2], sc[2 * ks + 1][3]);
#pragma unroll
            for (int nt = 0; nt < 16; nt++) {
                const int vb0 = vb + (ks * 8 + cq) * VROW + nt * 8 + r4;
                uint32_t bh[2] = {sw[vb0], sw[vb0 + 4 * VROW]};
                mmah(o[nt], ah, bh);
            }
        }
    }

    const float i0 = 1.0f / l0, i1 = 1.0f / l1;
    uint32_t* a0 = g_ah + (size_t)(b * S + q0 + w * 16 + r4) * KW + h * 64;
    uint32_t* a1 = g_ah + (size_t)(b * S + q0 + w * 16 + r4 + 8) * KW + h * 64;
#pragma unroll
    for (int nt = 0; nt < 16; nt++) {
        a0[nt * 4 + cq] = cvt2h(o[nt][0] * i0, o[nt][1] * i0);
        a1[nt * 4 + cq] = cvt2h(o[nt][2] * i1, o[nt][3] * i1);
    }
}

// ---------------- launch ----------------
extern "C" void kernel_launch(void* const* d_in, const int* in_sizes, int n_in,
                              void* d_out, int out_size) {
    const float* hs = (const float*)d_in[0];
    // d_in[1] = attention_mask: pure causal -> applied analytically
    const float* Wq = (const float*)d_in[2];
    const float* bq = (const float*)d_in[3];
    const float* Wk = (const float*)d_in[4];
    const float* bk = (const float*)d_in[5];
    const float* Wv = (const float*)d_in[6];
    const float* bv = (const float*)d_in[7];
    const float* Wo = (const float*)d_in[8];
    float* out = (float*)d_out;

    float *qp, *kp, *vp;
    cudaGetSymbolAddress((void**)&qp, g_q);
    cudaGetSymbolAddress((void**)&kp, g_k);
    cudaGetSymbolAddress((void**)&vp, g_v);

    cudaFuncSetAttribute(gemm_qkv, cudaFuncAttributeMaxDynamicSharedMemorySize, GEMM_SMEM);
    cudaFuncSetAttribute(gemm_o, cudaFuncAttributeMaxDynamicSharedMemorySize, GEMM_SMEM);
    cudaFuncSetAttribute(attn_mma, cudaFuncAttributeMaxDynamicSharedMemorySize, ATTN_SMEM);

    // #1: fused prep (weight+hs pack, RoPE table — FP64 confined here)
    prep_kernel<<<(N_PREP + 255) / 256, 256>>>(hs, Wq, Wk, Wv, Wo);
    // #2: QKV projection
    gemm_qkv<<<dim3(24, M / 128), 256, GEMM_SMEM>>>(bq, bk, bv, qp, kp, vp);
    // #3: fused RoPE apply + V pack
    rope_vconv_kernel<<<(N_ROPE + N_VC + 255) / 256, 256>>>();
    // #4: attention
    attn_mma<<<dim3(S / QT, NH, B), 128, ATTN_SMEM>>>();
    // #5: output projection
    gemm_o<<<dim3(HID / 128, M / 128), 256, GEMM_SMEM>>>(out);
}